// round 8
// baseline (speedup 1.0000x reference)
#include <cuda_runtime.h>

#define NNODE_MAX 100000
#define EDGE_MAX  3200000
#define HH 128
#define FIN 128
#define CC 40
#define LL 3

// ---------------- scratch (no allocations allowed) ----------------
__device__ float g_x[(size_t)NNODE_MAX * HH];
__device__ float g_hin[(size_t)NNODE_MAX * HH];
__device__ float g_m[(size_t)NNODE_MAX * HH];
__device__ float g_agg[(size_t)NNODE_MAX * HH];
__device__ float g_gi[(size_t)NNODE_MAX * 3 * HH];
__device__ float g_gh[(size_t)NNODE_MAX * 3 * HH];
__device__ float g_bnstats[2 * HH];
__device__ float g_scale[HH];
__device__ float g_shift[HH];
__device__ int   g_ei[(size_t)2 * EDGE_MAX];
__device__ int   g_flag[1];

// ---------------- edge_index dtype probe ----------------
__global__ void detect_idx_dtype(const long long* __restrict__ ei64, int M,
                                 int* __restrict__ flag)
{
    __shared__ int bad;
    if (threadIdx.x == 0) bad = 0;
    __syncthreads();
    long long v = ei64[threadIdx.x];
    if (v < 0 || v >= (long long)M) bad = 1;
    __syncthreads();
    if (threadIdx.x == 0) *flag = bad;
}

__global__ void convert_idx(const void* __restrict__ ei, int twoE,
                            const int* __restrict__ flag, int* __restrict__ out)
{
    int i = blockIdx.x * blockDim.x + threadIdx.x;
    if (i >= twoE) return;
    int v;
    if (*flag) v = ((const int*)ei)[i];
    else       v = (int)(((const long long*)ei)[i]);
    out[i] = v;
}

// ---------------- 128x128x16 register-tiled SGEMM, 8x8 micro-tile ----------
// C[M,Ncols] = A[M,K] @ B + bias
// bTrans==0 : B row-major [K, Ncols];  bTrans==1 : B stored [Ncols, K]
// If A2 != nullptr: A'[r,k] = A[r,k]*ascale[k] + ashift[k] + A2[r,k]
__global__ __launch_bounds__(256, 2) void sgemm128(
    const float* __restrict__ A, const float* __restrict__ B,
    const float* __restrict__ bias, float* __restrict__ C,
    int M, int Ncols, int K, int bTrans,
    const float* __restrict__ A2, const float* __restrict__ ascale,
    const float* __restrict__ ashift)
{
    __shared__ float As[16][132];   // padded: transposed A tile, As[k][m]
    __shared__ float Bs[16][128];   // Bs[k][n]

    const int tid = threadIdx.x;
    const int bm  = blockIdx.y * 128;
    const int bn  = blockIdx.x * 128;
    const int tx  = tid & 15;       // col group
    const int ty  = tid >> 4;       // row group
    const int crow = ty * 8;
    const int ccol = tx * 8;

    // A-tile loader: 128 rows x 16 k = 512 float4; 2 per thread
    const int aRow = tid >> 1;            // 0..127
    const int aK   = (tid & 1) * 8;       // 0 or 8

    float acc[8][8] = {};

    for (int k0 = 0; k0 < K; k0 += 16) {
        // ---- load A tile, store transposed ----
        {
            float4 a0 = make_float4(0.f, 0.f, 0.f, 0.f);
            float4 a1 = make_float4(0.f, 0.f, 0.f, 0.f);
            int gr = bm + aRow;
            if (gr < M) {
                const float* ap = A + (size_t)gr * K + k0 + aK;
                a0 = *reinterpret_cast<const float4*>(ap);
                a1 = *reinterpret_cast<const float4*>(ap + 4);
                if (A2 != nullptr) {
                    const float* a2p = A2 + (size_t)gr * K + k0 + aK;
                    float4 r0 = *reinterpret_cast<const float4*>(a2p);
                    float4 r1 = *reinterpret_cast<const float4*>(a2p + 4);
                    int kk = k0 + aK;
                    a0.x = a0.x * ascale[kk + 0] + ashift[kk + 0] + r0.x;
                    a0.y = a0.y * ascale[kk + 1] + ashift[kk + 1] + r0.y;
                    a0.z = a0.z * ascale[kk + 2] + ashift[kk + 2] + r0.z;
                    a0.w = a0.w * ascale[kk + 3] + ashift[kk + 3] + r0.w;
                    a1.x = a1.x * ascale[kk + 4] + ashift[kk + 4] + r1.x;
                    a1.y = a1.y * ascale[kk + 5] + ashift[kk + 5] + r1.y;
                    a1.z = a1.z * ascale[kk + 6] + ashift[kk + 6] + r1.z;
                    a1.w = a1.w * ascale[kk + 7] + ashift[kk + 7] + r1.w;
                }
            }
            As[aK + 0][aRow] = a0.x;
            As[aK + 1][aRow] = a0.y;
            As[aK + 2][aRow] = a0.z;
            As[aK + 3][aRow] = a0.w;
            As[aK + 4][aRow] = a1.x;
            As[aK + 5][aRow] = a1.y;
            As[aK + 6][aRow] = a1.z;
            As[aK + 7][aRow] = a1.w;
        }

        // ---- load B tile ----
        if (!bTrans) {
            const int bCol = (tid & 31) * 4;     // 0..124
            const int bRow0 = tid >> 5;          // 0..7
            #pragma unroll
            for (int hh = 0; hh < 2; hh++) {
                int row = bRow0 + hh * 8;
                int gn = bn + bCol;
                const float* bp = B + (size_t)(k0 + row) * Ncols + gn;
                float4 bv = make_float4(0.f, 0.f, 0.f, 0.f);
                if (gn + 3 < Ncols) {
                    bv = *reinterpret_cast<const float4*>(bp);
                } else {
                    if (gn + 0 < Ncols) bv.x = bp[0];
                    if (gn + 1 < Ncols) bv.y = bp[1];
                    if (gn + 2 < Ncols) bv.z = bp[2];
                    if (gn + 3 < Ncols) bv.w = bp[3];
                }
                *reinterpret_cast<float4*>(&Bs[row][bCol]) = bv;
            }
        } else {
            const int nI = tid & 127;            // 0..127
            const int kH = (tid >> 7) * 8;       // 0 or 8
            int gn = bn + nI;
            float4 b0 = make_float4(0.f, 0.f, 0.f, 0.f);
            float4 b1 = make_float4(0.f, 0.f, 0.f, 0.f);
            if (gn < Ncols) {
                const float* bp = B + (size_t)gn * K + k0 + kH;
                b0 = *reinterpret_cast<const float4*>(bp);
                b1 = *reinterpret_cast<const float4*>(bp + 4);
            }
            Bs[kH + 0][nI] = b0.x;
            Bs[kH + 1][nI] = b0.y;
            Bs[kH + 2][nI] = b0.z;
            Bs[kH + 3][nI] = b0.w;
            Bs[kH + 4][nI] = b1.x;
            Bs[kH + 5][nI] = b1.y;
            Bs[kH + 6][nI] = b1.z;
            Bs[kH + 7][nI] = b1.w;
        }
        __syncthreads();

        // ---- 8x8 micro-tile FMA over 16 k-steps ----
        #pragma unroll
        for (int k = 0; k < 16; k++) {
            float a[8], b[8];
            *reinterpret_cast<float4*>(&a[0]) = *reinterpret_cast<const float4*>(&As[k][crow]);
            *reinterpret_cast<float4*>(&a[4]) = *reinterpret_cast<const float4*>(&As[k][crow + 4]);
            *reinterpret_cast<float4*>(&b[0]) = *reinterpret_cast<const float4*>(&Bs[k][ccol]);
            *reinterpret_cast<float4*>(&b[4]) = *reinterpret_cast<const float4*>(&Bs[k][ccol + 4]);
            #pragma unroll
            for (int i = 0; i < 8; i++)
                #pragma unroll
                for (int j = 0; j < 8; j++)
                    acc[i][j] += a[i] * b[j];
        }
        __syncthreads();
    }

    // ---- epilogue ----
    #pragma unroll
    for (int i = 0; i < 8; i++) {
        int gr = bm + crow + i;
        if (gr >= M) continue;
        #pragma unroll
        for (int j = 0; j < 8; j++) {
            int gn = bn + ccol + j;
            if (gn < Ncols) {
                float v = acc[i][j];
                if (bias != nullptr) v += bias[gn];
                C[(size_t)gr * Ncols + gn] = v;
            }
        }
    }
}

// ---------------- zero fill ----------------
__global__ void zero_kernel(float* __restrict__ p, int n)
{
    int i = blockIdx.x * blockDim.x + threadIdx.x;
    if (i < n) p[i] = 0.f;
}

// ---------------- edge gather + weighted scatter-add ----------------
__global__ void edge_scatter(const int* __restrict__ srcdst,
                             const float* __restrict__ ew,
                             const float* __restrict__ m,
                             float* __restrict__ agg, int E)
{
    long long gt = (long long)blockIdx.x * blockDim.x + threadIdx.x;
    int e = (int)(gt >> 5);
    if (e >= E) return;
    int lane = threadIdx.x & 31;
    int src = srcdst[e];
    int dst = srcdst[E + e];
    float w = ew[e];
    float4 v = *reinterpret_cast<const float4*>(m + ((size_t)src << 7) + lane * 4);
    float* dp = agg + ((size_t)dst << 7) + lane * 4;
    asm volatile("red.global.add.v4.f32 [%0], {%1, %2, %3, %4};"
                 :: "l"(dp), "f"(v.x * w), "f"(v.y * w), "f"(v.z * w), "f"(v.w * w)
                 : "memory");
}

// ---------------- GRU elementwise update (in-place on x) ----------------
__global__ void gru_update(const float* __restrict__ gi, const float* __restrict__ gh,
                           float* __restrict__ x, int total)
{
    int idx = blockIdx.x * blockDim.x + threadIdx.x;
    if (idx >= total) return;
    int n = idx >> 7;
    int c = idx & 127;
    size_t b = (size_t)n * 384;
    float ir = gi[b + c],        hr = gh[b + c];
    float iz = gi[b + 128 + c],  hz = gh[b + 128 + c];
    float in_ = gi[b + 256 + c], hn = gh[b + 256 + c];
    float r = 1.f / (1.f + expf(-(ir + hr)));
    float z = 1.f / (1.f + expf(-(iz + hz)));
    float nn = tanhf(in_ + r * hn);
    x[idx] = (1.f - z) * nn + z * x[idx];
}

// ---------------- BatchNorm column statistics ----------------
__global__ void bn_stats(const float* __restrict__ x, float* __restrict__ bnSum,
                         float* __restrict__ bnSq, int M)
{
    int c = threadIdx.x;
    int r0 = blockIdx.x * 128;
    float s = 0.f, sq = 0.f;
    #pragma unroll 4
    for (int i = 0; i < 128; i++) {
        int r = r0 + i;
        if (r < M) {
            float v = x[(size_t)r * HH + c];
            s += v;
            sq += v * v;
        }
    }
    atomicAdd(&bnSum[c], s);
    atomicAdd(&bnSq[c], sq);
}

__global__ void bn_final(const float* __restrict__ bnSum, const float* __restrict__ bnSq,
                         const float* __restrict__ gamma, const float* __restrict__ beta,
                         float* __restrict__ scale, float* __restrict__ shift, int M)
{
    int c = threadIdx.x;
    float invN = 1.f / (float)M;
    float mean = bnSum[c] * invN;
    float var = bnSq[c] * invN - mean * mean;
    float sc = gamma[c] * rsqrtf(var + 1e-5f);
    scale[c] = sc;
    shift[c] = beta[c] - mean * sc;
}

// ---------------- launch ----------------
extern "C" void kernel_launch(void* const* d_in, const int* in_sizes, int n_in,
                              void* d_out, int out_size)
{
    const float* h      = (const float*)d_in[0];
    const void*  ei_raw = d_in[1];
    const float* ew     = (const float*)d_in[2];
    const float* emb_W  = (const float*)d_in[3];
    const float* emb_b  = (const float*)d_in[4];
    const float* conv_w = (const float*)d_in[5];
    const float* Wih    = (const float*)d_in[6];
    const float* Whh    = (const float*)d_in[7];
    const float* bih    = (const float*)d_in[8];
    const float* bhh    = (const float*)d_in[9];
    const float* gamma  = (const float*)d_in[10];
    const float* beta   = (const float*)d_in[11];
    const float* mlp_W  = (const float*)d_in[12];
    const float* mlp_b  = (const float*)d_in[13];
    float* out = (float*)d_out;

    const int M = in_sizes[0] / FIN;
    const int E = in_sizes[2];

    float *px, *phin, *pm, *pagg, *pgi, *pgh, *pbn, *pscale, *pshift;
    int *pei, *pflag;
    cudaGetSymbolAddress((void**)&px,     g_x);
    cudaGetSymbolAddress((void**)&phin,   g_hin);
    cudaGetSymbolAddress((void**)&pm,     g_m);
    cudaGetSymbolAddress((void**)&pagg,   g_agg);
    cudaGetSymbolAddress((void**)&pgi,    g_gi);
    cudaGetSymbolAddress((void**)&pgh,    g_gh);
    cudaGetSymbolAddress((void**)&pbn,    g_bnstats);
    cudaGetSymbolAddress((void**)&pscale, g_scale);
    cudaGetSymbolAddress((void**)&pshift, g_shift);
    cudaGetSymbolAddress((void**)&pei,    g_ei);
    cudaGetSymbolAddress((void**)&pflag,  g_flag);

    const dim3 blk(256);
    const int total = M * HH;
    const int mb = (M + 127) / 128;

    // 0. edge_index dtype probe + conversion to int32
    detect_idx_dtype<<<1, 1024>>>((const long long*)ei_raw, M, pflag);
    convert_idx<<<(2 * E + 255) / 256, 256>>>(ei_raw, 2 * E, pflag, pei);

    // 1. x = h @ emb_W + emb_b ; h_in = x
    sgemm128<<<dim3(1, mb), blk>>>(
        h, emb_W, emb_b, px, M, HH, FIN, 0, nullptr, nullptr, nullptr);
    cudaMemcpyAsync(phin, px, (size_t)total * sizeof(float), cudaMemcpyDeviceToDevice);

    // 2. L GatedGraphConv GRU steps
    for (int l = 0; l < LL; l++) {
        sgemm128<<<dim3(1, mb), blk>>>(
            px, conv_w + (size_t)l * HH * HH, nullptr, pm, M, HH, HH, 0,
            nullptr, nullptr, nullptr);
        zero_kernel<<<(total + 255) / 256, 256>>>(pagg, total);
        long long tth = (long long)E * 32;
        edge_scatter<<<(unsigned)((tth + 255) / 256), 256>>>(pei, ew, pm, pagg, E);
        sgemm128<<<dim3(3, mb), blk>>>(
            pagg, Wih, bih, pgi, M, 3 * HH, HH, 1, nullptr, nullptr, nullptr);
        sgemm128<<<dim3(3, mb), blk>>>(
            px, Whh, bhh, pgh, M, 3 * HH, HH, 1, nullptr, nullptr, nullptr);
        gru_update<<<(total + 255) / 256, 256>>>(pgi, pgh, px, total);
    }

    // 3. BatchNorm statistics -> per-feature scale/shift
    zero_kernel<<<1, 256>>>(pbn, 2 * HH);
    bn_stats<<<(M + 127) / 128, 128>>>(px, pbn, pbn + HH, M);
    bn_final<<<1, HH>>>(pbn, pbn + HH, gamma, beta, pscale, pshift, M);

    // 4. out = (BN(x) + h_in) @ mlp_W + mlp_b
    sgemm128<<<dim3(1, mb), blk>>>(
        px, mlp_W, mlp_b, out, M, CC, FIN, 0, phin, pscale, pshift);
}

// round 14
// speedup vs baseline: 1.3448x; 1.3448x over previous
#include <cuda_runtime.h>
#include <cuda_bf16.h>
#include <cstdint>

#define NNODE_MAX 100000
#define EDGE_MAX  3200000
#define HH 128
#define FIN 128
#define CC 40
#define LL 3

// ---------------- scratch ----------------
__device__ float g_x[(size_t)NNODE_MAX * HH];
__device__ float g_hin[(size_t)NNODE_MAX * HH];
__device__ float g_agg[(size_t)NNODE_MAX * HH];
__device__ float g_gi[(size_t)NNODE_MAX * 3 * HH];
__device__ float g_gh[(size_t)NNODE_MAX * 3 * HH];
__device__ __nv_bfloat16 g_xh[(size_t)NNODE_MAX * HH];
__device__ __nv_bfloat16 g_xl[(size_t)NNODE_MAX * HH];
__device__ __nv_bfloat16 g_ah[(size_t)NNODE_MAX * HH];
__device__ __nv_bfloat16 g_al[(size_t)NNODE_MAX * HH];
__device__ float         g_wgf[3 * 384 * 128];
__device__ __nv_bfloat16 g_wgh[3 * 384 * 128], g_wgl[3 * 384 * 128];
__device__ __nv_bfloat16 g_whh[384 * 128], g_whl[384 * 128];
__device__ __nv_bfloat16 g_eth[128 * 128], g_etl[128 * 128];
__device__ float g_bnstats[2 * HH];
__device__ float g_scale[HH], g_shift[HH];
__device__ int   g_ei[(size_t)2 * EDGE_MAX];
__device__ int   g_flag[1];

// ---------------- mma helpers (base-target instructions only) ----------------
__device__ __forceinline__ uint32_t smem_u32(const void* p) {
    uint32_t a;
    asm("{ .reg .u64 t; cvta.to.shared.u64 t, %1; cvt.u32.u64 %0, t; }" : "=r"(a) : "l"(p));
    return a;
}
__device__ __forceinline__ void ldsm4(uint32_t addr, uint32_t* r) {
    asm volatile("ldmatrix.sync.aligned.m8n8.x4.shared.b16 {%0,%1,%2,%3}, [%4];"
        : "=r"(r[0]), "=r"(r[1]), "=r"(r[2]), "=r"(r[3]) : "r"(addr));
}
__device__ __forceinline__ void mma16816(float* d, const uint32_t* a, uint32_t b0, uint32_t b1) {
    asm volatile("mma.sync.aligned.m16n8k16.row.col.f32.bf16.bf16.f32 "
        "{%0,%1,%2,%3}, {%4,%5,%6,%7}, {%8,%9}, {%0,%1,%2,%3};"
        : "+f"(d[0]), "+f"(d[1]), "+f"(d[2]), "+f"(d[3])
        : "r"(a[0]), "r"(a[1]), "r"(a[2]), "r"(a[3]), "r"(b0), "r"(b1));
}

// smem tile layout: 128 rows x 128 bf16; row stride 256B; 16B chunk cc stored at
// (cc ^ (row & 7)) -> conflict-free ldmatrix reads and chunked writes.
#define TILE_BYTES 32768
#define SMEM_MMA (4 * TILE_BYTES)

__device__ __forceinline__ void load_tile(const __nv_bfloat16* __restrict__ g,
                                          int row0, int maxRow, char* dst) {
    for (int idx = threadIdx.x; idx < 2048; idx += 256) {
        int r = idx >> 4, cc = idx & 15;
        uint4 v = make_uint4(0u, 0u, 0u, 0u);
        int gr = row0 + r;
        if (gr < maxRow) v = *reinterpret_cast<const uint4*>(g + (size_t)gr * 128 + cc * 8);
        *reinterpret_cast<uint4*>(dst + r * 256 + ((cc ^ (r & 7)) * 16)) = v;
    }
}

// C[M,N] = (Ah+Al)[M,128] . (Bh+Bl)[N,128]^T   (3-term bf16 split, fp32 acc)
__global__ __launch_bounds__(256, 1)
void mma_gemm(const __nv_bfloat16* __restrict__ Ah, const __nv_bfloat16* __restrict__ Al,
              const __nv_bfloat16* __restrict__ Bh, const __nv_bfloat16* __restrict__ Bl,
              float* __restrict__ C, int M, int N)
{
    extern __shared__ char smem[];
    char* sA = smem;                       // Ah @0, Al @TILE
    char* sB = smem + 2 * TILE_BYTES;      // Bh @0, Bl @TILE
    const uint32_t sbA = smem_u32(sA);
    const uint32_t sbB = smem_u32(sB);

    const int tid  = threadIdx.x;
    const int wid  = tid >> 5;
    const int lane = tid & 31;
    const int wm0  = (wid >> 1) * 32;      // warp row offset (0,32,64,96)
    const int wn0  = (wid & 1) * 64;       // warp col offset (0,64)

    // ldmatrix lane geometry: group g = lane>>3 selects (subrow +8?, chunk +1?)
    const int lg   = lane >> 3;
    const int lri  = (lane & 7) + ((lg & 1) << 3);   // row-in-16
    const int lch  = lg >> 1;                        // chunk offset 0/1

    const int bm = blockIdx.x * 128;
    load_tile(Ah, bm, M, sA);
    load_tile(Al, bm, M, sA + TILE_BYTES);

    const int nch = N >> 7;
    for (int nc = 0; nc < nch; nc++) {
        load_tile(Bh, nc * 128, N, sB);
        load_tile(Bl, nc * 128, N, sB + TILE_BYTES);
        __syncthreads();

        float acc[2][8][4];
        #pragma unroll
        for (int i = 0; i < 2; i++)
            #pragma unroll
            for (int j = 0; j < 8; j++)
                #pragma unroll
                for (int q = 0; q < 4; q++) acc[i][j][q] = 0.f;

        #pragma unroll
        for (int sp = 0; sp < 3; sp++) {
            const uint32_t aBase = sbA + (sp == 2 ? TILE_BYTES : 0);
            const uint32_t bBase = sbB + (sp == 1 ? TILE_BYTES : 0);
            #pragma unroll
            for (int ks = 0; ks < 8; ks++) {
                const int chunk = ks * 2 + lch;
                uint32_t a[2][4], b[4][4];
                #pragma unroll
                for (int i = 0; i < 2; i++) {
                    int row = wm0 + i * 16 + lri;
                    ldsm4(aBase + row * 256 + ((chunk ^ (row & 7)) * 16), a[i]);
                }
                #pragma unroll
                for (int j = 0; j < 4; j++) {
                    int row = wn0 + j * 16 + lri;
                    ldsm4(bBase + row * 256 + ((chunk ^ (row & 7)) * 16), b[j]);
                }
                #pragma unroll
                for (int i = 0; i < 2; i++)
                    #pragma unroll
                    for (int j = 0; j < 4; j++) {
                        mma16816(acc[i][2 * j],     a[i], b[j][0], b[j][2]);
                        mma16816(acc[i][2 * j + 1], a[i], b[j][1], b[j][3]);
                    }
            }
        }

        // epilogue: d frag (r=lane>>2, c=(lane&3)*2) and (r+8, c)
        const int fr = lane >> 2, fc = (lane & 3) * 2;
        #pragma unroll
        for (int i = 0; i < 2; i++) {
            #pragma unroll
            for (int j = 0; j < 8; j++) {
                int col = nc * 128 + wn0 + j * 8 + fc;
                int r0 = bm + wm0 + i * 16 + fr;
                if (r0 < M)
                    *reinterpret_cast<float2*>(C + (size_t)r0 * N + col) =
                        make_float2(acc[i][j][0], acc[i][j][1]);
                if (r0 + 8 < M)
                    *reinterpret_cast<float2*>(C + (size_t)(r0 + 8) * N + col) =
                        make_float2(acc[i][j][2], acc[i][j][3]);
            }
        }
        __syncthreads();
    }
}

// ---------------- splits ----------------
__global__ void split_bf16(const float* __restrict__ in, __nv_bfloat16* __restrict__ hi,
                           __nv_bfloat16* __restrict__ lo, int n)
{
    int i = (blockIdx.x * blockDim.x + threadIdx.x) * 4;
    if (i >= n) return;
    float4 v = *reinterpret_cast<const float4*>(in + i);
    __nv_bfloat16 h0 = __float2bfloat16(v.x), h1 = __float2bfloat16(v.y);
    __nv_bfloat16 h2 = __float2bfloat16(v.z), h3 = __float2bfloat16(v.w);
    *reinterpret_cast<__nv_bfloat162*>(hi + i)     = __nv_bfloat162(h0, h1);
    *reinterpret_cast<__nv_bfloat162*>(hi + i + 2) = __nv_bfloat162(h2, h3);
    *reinterpret_cast<__nv_bfloat162*>(lo + i) = __nv_bfloat162(
        __float2bfloat16(v.x - __bfloat162float(h0)), __float2bfloat16(v.y - __bfloat162float(h1)));
    *reinterpret_cast<__nv_bfloat162*>(lo + i + 2) = __nv_bfloat162(
        __float2bfloat16(v.z - __bfloat162float(h2)), __float2bfloat16(v.w - __bfloat162float(h3)));
}
__global__ void trans_split_128(const float* __restrict__ in, __nv_bfloat16* __restrict__ hi,
                                __nv_bfloat16* __restrict__ lo)
{
    int idx = blockIdx.x * blockDim.x + threadIdx.x;
    if (idx >= 128 * 128) return;
    int n = idx >> 7, k = idx & 127;
    float v = in[k * 128 + n];
    __nv_bfloat16 h = __float2bfloat16(v);
    hi[idx] = h;
    lo[idx] = __float2bfloat16(v - __bfloat162float(h));
}

// ---------------- fp32 SGEMM 64x64 (mlp + weight prep) ----------------
__global__ __launch_bounds__(256) void sgemm64(
    const float* __restrict__ A, const float* __restrict__ B,
    const float* __restrict__ bias, float* __restrict__ C,
    int M, int Ncols, int K, int bTrans,
    const float* __restrict__ A2, const float* __restrict__ ascale,
    const float* __restrict__ ashift)
{
    __shared__ float As[16][64];
    __shared__ float Bs[16][64];
    const int tid = threadIdx.x;
    const int bm = blockIdx.y * 64, bn = blockIdx.x * 64;
    const int trow = (tid >> 4) << 2, tcol = (tid & 15) << 2;
    const int aRow = tid >> 2, aCol = (tid & 3) << 2;
    const int bRow = tid >> 4, bCol = (tid & 15) << 2;
    float acc[4][4] = {};

    for (int k0 = 0; k0 < K; k0 += 16) {
        float4 av = make_float4(0.f, 0.f, 0.f, 0.f);
        int gr = bm + aRow;
        if (gr < M) {
            av = *reinterpret_cast<const float4*>(A + (size_t)gr * K + k0 + aCol);
            if (A2 != nullptr) {
                float4 a2 = *reinterpret_cast<const float4*>(A2 + (size_t)gr * K + k0 + aCol);
                int kk = k0 + aCol;
                av.x = av.x * ascale[kk+0] + ashift[kk+0] + a2.x;
                av.y = av.y * ascale[kk+1] + ashift[kk+1] + a2.y;
                av.z = av.z * ascale[kk+2] + ashift[kk+2] + a2.z;
                av.w = av.w * ascale[kk+3] + ashift[kk+3] + a2.w;
            }
        }
        As[aCol+0][aRow] = av.x; As[aCol+1][aRow] = av.y;
        As[aCol+2][aRow] = av.z; As[aCol+3][aRow] = av.w;

        if (!bTrans) {
            int gn = bn + bCol;
            const float* bp = B + (size_t)(k0 + bRow) * Ncols + gn;
            float4 bv = make_float4(0.f, 0.f, 0.f, 0.f);
            if (gn + 3 < Ncols) bv = *reinterpret_cast<const float4*>(bp);
            else {
                if (gn+0 < Ncols) bv.x = bp[0];
                if (gn+1 < Ncols) bv.y = bp[1];
                if (gn+2 < Ncols) bv.z = bp[2];
                if (gn+3 < Ncols) bv.w = bp[3];
            }
            Bs[bRow][bCol+0] = bv.x; Bs[bRow][bCol+1] = bv.y;
            Bs[bRow][bCol+2] = bv.z; Bs[bRow][bCol+3] = bv.w;
        } else {
            int nIdx = tid >> 2, kIdx = (tid & 3) << 2;
            int gn = bn + nIdx;
            float4 bv = make_float4(0.f, 0.f, 0.f, 0.f);
            if (gn < Ncols) bv = *reinterpret_cast<const float4*>(B + (size_t)gn * K + k0 + kIdx);
            Bs[kIdx+0][nIdx] = bv.x; Bs[kIdx+1][nIdx] = bv.y;
            Bs[kIdx+2][nIdx] = bv.z; Bs[kIdx+3][nIdx] = bv.w;
        }
        __syncthreads();
        #pragma unroll
        for (int k = 0; k < 16; k++) {
            float4 a = *reinterpret_cast<const float4*>(&As[k][trow]);
            float4 b = *reinterpret_cast<const float4*>(&Bs[k][tcol]);
            acc[0][0] += a.x*b.x; acc[0][1] += a.x*b.y; acc[0][2] += a.x*b.z; acc[0][3] += a.x*b.w;
            acc[1][0] += a.y*b.x; acc[1][1] += a.y*b.y; acc[1][2] += a.y*b.z; acc[1][3] += a.y*b.w;
            acc[2][0] += a.z*b.x; acc[2][1] += a.z*b.y; acc[2][2] += a.z*b.z; acc[2][3] += a.z*b.w;
            acc[3][0] += a.w*b.x; acc[3][1] += a.w*b.y; acc[3][2] += a.w*b.z; acc[3][3] += a.w*b.w;
        }
        __syncthreads();
    }
    #pragma unroll
    for (int i = 0; i < 4; i++) {
        int gr = bm + trow + i;
        if (gr >= M) continue;
        #pragma unroll
        for (int j = 0; j < 4; j++) {
            int gn = bn + tcol + j;
            if (gn < Ncols) {
                float v = acc[i][j];
                if (bias != nullptr) v += bias[gn];
                C[(size_t)gr * Ncols + gn] = v;
            }
        }
    }
}

// ---------------- misc ----------------
__global__ void detect_idx_dtype(const long long* __restrict__ ei64, int M, int* __restrict__ flag)
{
    __shared__ int bad;
    if (threadIdx.x == 0) bad = 0;
    __syncthreads();
    long long v = ei64[threadIdx.x];
    if (v < 0 || v >= (long long)M) bad = 1;
    __syncthreads();
    if (threadIdx.x == 0) *flag = bad;
}
__global__ void convert_idx(const void* __restrict__ ei, int twoE,
                            const int* __restrict__ flag, int* __restrict__ out)
{
    int i = blockIdx.x * blockDim.x + threadIdx.x;
    if (i >= twoE) return;
    out[i] = *flag ? ((const int*)ei)[i] : (int)(((const long long*)ei)[i]);
}
__global__ void zero_kernel(float* __restrict__ p, int n)
{
    int i = blockIdx.x * blockDim.x + threadIdx.x;
    if (i < n) p[i] = 0.f;
}
__global__ void edge_scatter(const int* __restrict__ srcdst, const float* __restrict__ ew,
                             const float* __restrict__ x, float* __restrict__ agg, int E)
{
    long long gt = (long long)blockIdx.x * blockDim.x + threadIdx.x;
    int e = (int)(gt >> 5);
    if (e >= E) return;
    int lane = threadIdx.x & 31;
    int src = srcdst[e], dst = srcdst[E + e];
    float w = ew[e];
    float4 v = *reinterpret_cast<const float4*>(x + ((size_t)src << 7) + lane * 4);
    float* dp = agg + ((size_t)dst << 7) + lane * 4;
    asm volatile("red.global.add.v4.f32 [%0], {%1, %2, %3, %4};"
                 :: "l"(dp), "f"(v.x*w), "f"(v.y*w), "f"(v.z*w), "f"(v.w*w) : "memory");
}
__global__ void post_emb(float* __restrict__ x, const float* __restrict__ eb,
                         float* __restrict__ hin, __nv_bfloat16* __restrict__ xh,
                         __nv_bfloat16* __restrict__ xl, int total)
{
    int idx = blockIdx.x * blockDim.x + threadIdx.x;
    if (idx >= total) return;
    float v = x[idx] + eb[idx & 127];
    x[idx] = v; hin[idx] = v;
    __nv_bfloat16 h = __float2bfloat16(v);
    xh[idx] = h;
    xl[idx] = __float2bfloat16(v - __bfloat162float(h));
}
__global__ void gru_update(const float* __restrict__ gi, const float* __restrict__ gh,
                           const float* __restrict__ bih, const float* __restrict__ bhh,
                           float* __restrict__ x, __nv_bfloat16* __restrict__ xh,
                           __nv_bfloat16* __restrict__ xl, int total)
{
    int idx = blockIdx.x * blockDim.x + threadIdx.x;
    if (idx >= total) return;
    int c = idx & 127;
    size_t b = (size_t)(idx >> 7) * 384;
    float ir = gi[b+c]     + bih[c],     hr = gh[b+c]     + bhh[c];
    float iz = gi[b+128+c] + bih[128+c], hz = gh[b+128+c] + bhh[128+c];
    float in_ = gi[b+256+c] + bih[256+c], hn = gh[b+256+c] + bhh[256+c];
    float r = 1.f / (1.f + expf(-(ir + hr)));
    float z = 1.f / (1.f + expf(-(iz + hz)));
    float nn = tanhf(in_ + r * hn);
    float xn = (1.f - z) * nn + z * x[idx];
    x[idx] = xn;
    __nv_bfloat16 h = __float2bfloat16(xn);
    xh[idx] = h;
    xl[idx] = __float2bfloat16(xn - __bfloat162float(h));
}
__global__ void bn_stats(const float* __restrict__ x, float* __restrict__ bnSum,
                         float* __restrict__ bnSq, int M)
{
    int c = threadIdx.x, r0 = blockIdx.x * 128;
    float s = 0.f, sq = 0.f;
    #pragma unroll 4
    for (int i = 0; i < 128; i++) {
        int r = r0 + i;
        if (r < M) { float v = x[(size_t)r * HH + c]; s += v; sq += v * v; }
    }
    atomicAdd(&bnSum[c], s);
    atomicAdd(&bnSq[c], sq);
}
__global__ void bn_final(const float* __restrict__ bnSum, const float* __restrict__ bnSq,
                         const float* __restrict__ gamma, const float* __restrict__ beta,
                         float* __restrict__ scale, float* __restrict__ shift, int M)
{
    int c = threadIdx.x;
    float invN = 1.f / (float)M;
    float mean = bnSum[c] * invN;
    float var = bnSq[c] * invN - mean * mean;
    float sc = gamma[c] * rsqrtf(var + 1e-5f);
    scale[c] = sc;
    shift[c] = beta[c] - mean * sc;
}

// ---------------- launch ----------------
extern "C" void kernel_launch(void* const* d_in, const int* in_sizes, int n_in,
                              void* d_out, int out_size)
{
    const float* h      = (const float*)d_in[0];
    const void*  ei_raw = d_in[1];
    const float* ew     = (const float*)d_in[2];
    const float* emb_W  = (const float*)d_in[3];
    const float* emb_b  = (const float*)d_in[4];
    const float* conv_w = (const float*)d_in[5];
    const float* Wih    = (const float*)d_in[6];
    const float* Whh    = (const float*)d_in[7];
    const float* bih    = (const float*)d_in[8];
    const float* bhh    = (const float*)d_in[9];
    const float* gamma  = (const float*)d_in[10];
    const float* beta   = (const float*)d_in[11];
    const float* mlp_W  = (const float*)d_in[12];
    const float* mlp_b  = (const float*)d_in[13];
    float* out = (float*)d_out;

    const int M = in_sizes[0] / FIN;
    const int E = in_sizes[2];

    float *px, *phin, *pagg, *pgi, *pgh, *pbn, *pscale, *pshift, *pwgf;
    __nv_bfloat16 *pxh, *pxl, *pah, *pal, *pwgh, *pwgl, *pwhh, *pwhl, *peth, *petl;
    int *pei, *pflag;
    cudaGetSymbolAddress((void**)&px, g_x);       cudaGetSymbolAddress((void**)&phin, g_hin);
    cudaGetSymbolAddress((void**)&pagg, g_agg);   cudaGetSymbolAddress((void**)&pgi, g_gi);
    cudaGetSymbolAddress((void**)&pgh, g_gh);     cudaGetSymbolAddress((void**)&pbn, g_bnstats);
    cudaGetSymbolAddress((void**)&pscale, g_scale); cudaGetSymbolAddress((void**)&pshift, g_shift);
    cudaGetSymbolAddress((void**)&pxh, g_xh);     cudaGetSymbolAddress((void**)&pxl, g_xl);
    cudaGetSymbolAddress((void**)&pah, g_ah);     cudaGetSymbolAddress((void**)&pal, g_al);
    cudaGetSymbolAddress((void**)&pwgf, g_wgf);
    cudaGetSymbolAddress((void**)&pwgh, g_wgh);   cudaGetSymbolAddress((void**)&pwgl, g_wgl);
    cudaGetSymbolAddress((void**)&pwhh, g_whh);   cudaGetSymbolAddress((void**)&pwhl, g_whl);
    cudaGetSymbolAddress((void**)&peth, g_eth);   cudaGetSymbolAddress((void**)&petl, g_etl);
    cudaGetSymbolAddress((void**)&pei, g_ei);     cudaGetSymbolAddress((void**)&pflag, g_flag);

    cudaFuncSetAttribute(mma_gemm, cudaFuncAttributeMaxDynamicSharedMemorySize, SMEM_MMA);

    const int total = M * HH;
    const int mb = (M + 127) / 128;

    // 0. edge index conversion
    detect_idx_dtype<<<1, 1024>>>((const long long*)ei_raw, M, pflag);
    convert_idx<<<(2 * E + 255) / 256, 256>>>(ei_raw, 2 * E, pflag, pei);

    // weight prep: Wg[l] = Wih @ conv_w[l]^T ([384,128]); split everything
    split_bf16<<<(384 * 128 / 4 + 255) / 256, 256>>>(Whh, pwhh, pwhl, 384 * 128);
    trans_split_128<<<(128 * 128 + 255) / 256, 256>>>(emb_W, peth, petl);
    for (int l = 0; l < LL; l++) {
        sgemm64<<<dim3(2, 6), 256>>>(Wih, conv_w + (size_t)l * 128 * 128, nullptr,
                                     pwgf + (size_t)l * 384 * 128, 384, 128, 128, 1,
                                     nullptr, nullptr, nullptr);
        split_bf16<<<(384 * 128 / 4 + 255) / 256, 256>>>(
            pwgf + (size_t)l * 384 * 128, pwgh + (size_t)l * 384 * 128,
            pwgl + (size_t)l * 384 * 128, 384 * 128);
    }

    // 1. x = h @ emb_W + b (mma), residual + split
    split_bf16<<<(total / 4 + 255) / 256, 256>>>(h, pah, pal, total);
    mma_gemm<<<mb, 256, SMEM_MMA>>>(pah, pal, peth, petl, px, M, 128);
    post_emb<<<(total + 255) / 256, 256>>>(px, emb_b, phin, pxh, pxl, total);

    // 2. GRU layers: agg = scatter(w*x); gi = agg@Wg[l]^T; gh = x@Whh^T
    for (int l = 0; l < LL; l++) {
        zero_kernel<<<(total + 255) / 256, 256>>>(pagg, total);
        long long tth = (long long)E * 32;
        edge_scatter<<<(unsigned)((tth + 255) / 256), 256>>>(pei, ew, px, pagg, E);
        split_bf16<<<(total / 4 + 255) / 256, 256>>>(pagg, pah, pal, total);
        mma_gemm<<<mb, 256, SMEM_MMA>>>(pah, pal, pwgh + (size_t)l * 384 * 128,
                                        pwgl + (size_t)l * 384 * 128, pgi, M, 384);
        mma_gemm<<<mb, 256, SMEM_MMA>>>(pxh, pxl, pwhh, pwhl, pgh, M, 384);
        gru_update<<<(total + 255) / 256, 256>>>(pgi, pgh, bih, bhh, px, pxh, pxl, total);
    }

    // 3. BN -> scale/shift
    zero_kernel<<<1, 256>>>(pbn, 2 * HH);
    bn_stats<<<(M + 127) / 128, 128>>>(px, pbn, pbn + HH, M);
    bn_final<<<1, HH>>>(pbn, pbn + HH, gamma, beta, pscale, pshift, M);

    // 4. out = (BN(x) + h_in) @ mlp_W + mlp_b  (fp32, BN+residual fused)
    sgemm64<<<dim3(1, (M + 63) / 64), 256>>>(
        px, mlp_W, mlp_b, out, M, CC, FIN, 0, phin, pscale, pshift);
}

// round 15
// speedup vs baseline: 1.7503x; 1.3016x over previous
#include <cuda_runtime.h>
#include <cuda_bf16.h>
#include <cstdint>

#define NNODE_MAX 100000
#define EDGE_MAX  3200000
#define HH 128
#define FIN 128
#define CC 40
#define LL 3

// ---------------- scratch ----------------
__device__ float g_x[(size_t)NNODE_MAX * HH];
__device__ float g_hin[(size_t)NNODE_MAX * HH];
__device__ float g_G[(size_t)NNODE_MAX * 2 * HH];    // summed r,z pre-activations
__device__ float g_gn[(size_t)NNODE_MAX * 2 * HH];   // [0:N*128) i_n, [N*128:) h_n
__device__ __nv_bfloat16 g_xh[(size_t)NNODE_MAX * HH];
__device__ __nv_bfloat16 g_xl[(size_t)NNODE_MAX * HH];
__device__ __nv_bfloat16 g_ah[(size_t)NNODE_MAX * HH];
__device__ __nv_bfloat16 g_al[(size_t)NNODE_MAX * HH];
__device__ float         g_wgf[3 * 384 * 128];
__device__ __nv_bfloat16 g_wgh[3 * 384 * 128], g_wgl[3 * 384 * 128];
__device__ __nv_bfloat16 g_whh[384 * 128], g_whl[384 * 128];
__device__ __nv_bfloat16 g_eth[128 * 128], g_etl[128 * 128];
__device__ float g_bnstats[2 * HH];
__device__ float g_scale[HH], g_shift[HH];
__device__ int   g_ei[(size_t)2 * EDGE_MAX];
__device__ int   g_flag[1];
__device__ int   g_deg[NNODE_MAX];
__device__ int   g_rowptr[NNODE_MAX + 1];
__device__ int   g_cursor[NNODE_MAX];
__device__ int2  g_csr[EDGE_MAX];   // (src, weight bits) sorted by dst

// ---------------- mma helpers ----------------
__device__ __forceinline__ uint32_t smem_u32(const void* p) {
    uint32_t a;
    asm("{ .reg .u64 t; cvta.to.shared.u64 t, %1; cvt.u32.u64 %0, t; }" : "=r"(a) : "l"(p));
    return a;
}
__device__ __forceinline__ void ldsm4(uint32_t addr, uint32_t* r) {
    asm volatile("ldmatrix.sync.aligned.m8n8.x4.shared.b16 {%0,%1,%2,%3}, [%4];"
        : "=r"(r[0]), "=r"(r[1]), "=r"(r[2]), "=r"(r[3]) : "r"(addr));
}
__device__ __forceinline__ void mma16816(float* d, const uint32_t* a, uint32_t b0, uint32_t b1) {
    asm volatile("mma.sync.aligned.m16n8k16.row.col.f32.bf16.bf16.f32 "
        "{%0,%1,%2,%3}, {%4,%5,%6,%7}, {%8,%9}, {%0,%1,%2,%3};"
        : "+f"(d[0]), "+f"(d[1]), "+f"(d[2]), "+f"(d[3])
        : "r"(a[0]), "r"(a[1]), "r"(a[2]), "r"(a[3]), "r"(b0), "r"(b1));
}
#define TILE_BYTES 32768

// smem tile: 128 rows x 128 bf16, row stride 256B, chunk cc at (cc ^ (r&7))
__device__ __forceinline__ void load_tile(const __nv_bfloat16* __restrict__ g,
                                          int row0, int maxRow, char* dst) {
    for (int idx = threadIdx.x; idx < 2048; idx += 256) {
        int r = idx >> 4, cc = idx & 15;
        uint4 v = make_uint4(0u, 0u, 0u, 0u);
        int gr = row0 + r;
        if (gr < maxRow) v = *reinterpret_cast<const uint4*>(g + (size_t)gr * 128 + cc * 8);
        *reinterpret_cast<uint4*>(dst + r * 256 + ((cc ^ (r & 7)) * 16)) = v;
    }
}

// one K=128 pass: acc += A(smem aBase) . B(smem bBase)^T for this warp's 32x64 tile
__device__ __forceinline__ void mma_block(uint32_t aBase, uint32_t bBase, int wm0, int wn0,
                                          int lri, int lch, float (&acc)[2][8][4]) {
    #pragma unroll
    for (int ks = 0; ks < 8; ks++) {
        const int chunk = ks * 2 + lch;
        uint32_t a[2][4], b[4][4];
        #pragma unroll
        for (int i = 0; i < 2; i++) {
            int row = wm0 + i * 16 + lri;
            ldsm4(aBase + row * 256 + ((chunk ^ (row & 7)) * 16), a[i]);
        }
        #pragma unroll
        for (int j = 0; j < 4; j++) {
            int row = wn0 + j * 16 + lri;
            ldsm4(bBase + row * 256 + ((chunk ^ (row & 7)) * 16), b[j]);
        }
        #pragma unroll
        for (int i = 0; i < 2; i++)
            #pragma unroll
            for (int j = 0; j < 4; j++) {
                mma16816(acc[i][2 * j],     a[i], b[j][0], b[j][2]);
                mma16816(acc[i][2 * j + 1], a[i], b[j][1], b[j][3]);
            }
    }
}
__device__ __forceinline__ void acc_zero(float (&acc)[2][8][4]) {
    #pragma unroll
    for (int i = 0; i < 2; i++)
        #pragma unroll
        for (int j = 0; j < 8; j++)
            #pragma unroll
            for (int q = 0; q < 4; q++) acc[i][j][q] = 0.f;
}
__device__ __forceinline__ void acc_store(float* out, int ncols, int colbase, int bm, int M,
                                          int wm0, int wn0, int lane, float (&acc)[2][8][4]) {
    const int fr = lane >> 2, fc = (lane & 3) * 2;
    #pragma unroll
    for (int i = 0; i < 2; i++)
        #pragma unroll
        for (int j = 0; j < 8; j++) {
            int col = colbase + wn0 + j * 8 + fc;
            int r0 = bm + wm0 + i * 16 + fr;
            if (r0 < M)
                *reinterpret_cast<float2*>(out + (size_t)r0 * ncols + col) =
                    make_float2(acc[i][j][0], acc[i][j][1]);
            if (r0 + 8 < M)
                *reinterpret_cast<float2*>(out + (size_t)(r0 + 8) * ncols + col) =
                    make_float2(acc[i][j][2], acc[i][j][3]);
        }
}

// ---- emb GEMM: C[M,128] = (Ah+Al).(Bh+Bl)^T, 3-term split ----
#define SMEM_MMA (4 * TILE_BYTES)
__global__ __launch_bounds__(256, 1)
void mma_gemm(const __nv_bfloat16* __restrict__ Ah, const __nv_bfloat16* __restrict__ Al,
              const __nv_bfloat16* __restrict__ Bh, const __nv_bfloat16* __restrict__ Bl,
              float* __restrict__ C, int M)
{
    extern __shared__ char smem[];
    const uint32_t sbA = smem_u32(smem), sbB = smem_u32(smem + 2 * TILE_BYTES);
    const int tid = threadIdx.x, wid = tid >> 5, lane = tid & 31;
    const int wm0 = (wid >> 1) * 32, wn0 = (wid & 1) * 64;
    const int lg = lane >> 3, lri = (lane & 7) + ((lg & 1) << 3), lch = lg >> 1;
    const int bm = blockIdx.x * 128;

    load_tile(Ah, bm, M, smem);
    load_tile(Al, bm, M, smem + TILE_BYTES);
    load_tile(Bh, 0, 128, smem + 2 * TILE_BYTES);
    load_tile(Bl, 0, 128, smem + 3 * TILE_BYTES);
    __syncthreads();
    float acc[2][8][4];
    acc_zero(acc);
    mma_block(sbA, sbB, wm0, wn0, lri, lch, acc);
    mma_block(sbA, sbB + TILE_BYTES, wm0, wn0, lri, lch, acc);
    mma_block(sbA + TILE_BYTES, sbB, wm0, wn0, lri, lch, acc);
    acc_store(C, 128, 0, bm, M, wm0, wn0, lane, acc);
}

// ---- fused GRU GEMM: G[:,0:256] = agg@Wg^T + x@Whh^T (r,z); gin/ghn separate ----
#define SMEM_GRU (6 * TILE_BYTES)
__global__ __launch_bounds__(256, 1)
void mma_gemm_gru(const __nv_bfloat16* __restrict__ A1h, const __nv_bfloat16* __restrict__ A1l,
                  const __nv_bfloat16* __restrict__ A2h, const __nv_bfloat16* __restrict__ A2l,
                  const __nv_bfloat16* __restrict__ B1h, const __nv_bfloat16* __restrict__ B1l,
                  const __nv_bfloat16* __restrict__ B2h, const __nv_bfloat16* __restrict__ B2l,
                  float* __restrict__ G, float* __restrict__ Gin, float* __restrict__ Ghn, int M)
{
    extern __shared__ char smem[];
    char* sB = smem + 4 * TILE_BYTES;
    const uint32_t sbA = smem_u32(smem), sbB = smem_u32(sB);
    const int tid = threadIdx.x, wid = tid >> 5, lane = tid & 31;
    const int wm0 = (wid >> 1) * 32, wn0 = (wid & 1) * 64;
    const int lg = lane >> 3, lri = (lane & 7) + ((lg & 1) << 3), lch = lg >> 1;
    const int bm = blockIdx.x * 128;
    const uint32_t a1h = sbA, a1l = sbA + TILE_BYTES;
    const uint32_t a2h = sbA + 2 * TILE_BYTES, a2l = sbA + 3 * TILE_BYTES;
    const uint32_t bh = sbB, bl = sbB + TILE_BYTES;

    load_tile(A1h, bm, M, smem);
    load_tile(A1l, bm, M, smem + TILE_BYTES);
    load_tile(A2h, bm, M, smem + 2 * TILE_BYTES);
    load_tile(A2l, bm, M, smem + 3 * TILE_BYTES);

    float acc[2][8][4];
    #pragma unroll
    for (int nc = 0; nc < 3; nc++) {
        __syncthreads();                       // prior sB consumers done (and A stores on nc=0)
        load_tile(B1h, nc * 128, 384, sB);
        load_tile(B1l, nc * 128, 384, sB + TILE_BYTES);
        __syncthreads();
        acc_zero(acc);
        mma_block(a1h, bh, wm0, wn0, lri, lch, acc);
        mma_block(a1h, bl, wm0, wn0, lri, lch, acc);
        mma_block(a1l, bh, wm0, wn0, lri, lch, acc);
        if (nc == 2) {                         // i_n: store separately, restart acc
            acc_store(Gin, 128, 0, bm, M, wm0, wn0, lane, acc);
        }
        __syncthreads();
        load_tile(B2h, nc * 128, 384, sB);
        load_tile(B2l, nc * 128, 384, sB + TILE_BYTES);
        __syncthreads();
        if (nc == 2) acc_zero(acc);
        mma_block(a2h, bh, wm0, wn0, lri, lch, acc);
        mma_block(a2h, bl, wm0, wn0, lri, lch, acc);
        mma_block(a2l, bh, wm0, wn0, lri, lch, acc);
        if (nc < 2) acc_store(G, 256, nc * 128, bm, M, wm0, wn0, lane, acc);
        else        acc_store(Ghn, 128, 0, bm, M, wm0, wn0, lane, acc);
    }
}

// ---------------- CSR build ----------------
__global__ void zero_int(int* __restrict__ p, int n)
{
    int i = blockIdx.x * blockDim.x + threadIdx.x;
    if (i < n) p[i] = 0;
}
__global__ void count_deg(const int* __restrict__ srcdst, int* __restrict__ deg, int E)
{
    int e = blockIdx.x * blockDim.x + threadIdx.x;
    if (e < E) atomicAdd(&deg[srcdst[E + e]], 1);
}
__global__ void scan_deg(const int* __restrict__ deg, int* __restrict__ rowptr,
                         int* __restrict__ cursor, int M)
{
    __shared__ int s[1024];
    __shared__ int carry;
    if (threadIdx.x == 0) { carry = 0; rowptr[0] = 0; }
    __syncthreads();
    for (int base = 0; base < M; base += 1024) {
        int i = base + threadIdx.x;
        int v = (i < M) ? deg[i] : 0;
        s[threadIdx.x] = v;
        __syncthreads();
        #pragma unroll
        for (int off = 1; off < 1024; off <<= 1) {
            int t = (threadIdx.x >= off) ? s[threadIdx.x - off] : 0;
            __syncthreads();
            s[threadIdx.x] += t;
            __syncthreads();
        }
        if (i < M) {
            int incl = carry + s[threadIdx.x];
            rowptr[i + 1] = incl;
            cursor[i] = incl - v;
        }
        __syncthreads();
        if (threadIdx.x == 0) carry += s[1023];
        __syncthreads();
    }
}
__global__ void fill_csr(const int* __restrict__ srcdst, const float* __restrict__ ew,
                         int* __restrict__ cursor, int2* __restrict__ csr, int E)
{
    int e = blockIdx.x * blockDim.x + threadIdx.x;
    if (e >= E) return;
    int pos = atomicAdd(&cursor[srcdst[E + e]], 1);
    csr[pos] = make_int2(srcdst[e], __float_as_int(ew[e]));
}

// ---- aggregate: warp per node; agg = sum w*x[src]; writes bf16 hi/lo split ----
__global__ void csr_aggregate(const int* __restrict__ rowptr, const int2* __restrict__ csr,
                              const float* __restrict__ x, __nv_bfloat16* __restrict__ ah,
                              __nv_bfloat16* __restrict__ al, int M)
{
    int node = (int)((blockIdx.x * blockDim.x + threadIdx.x) >> 5);
    if (node >= M) return;
    int lane = threadIdx.x & 31;
    int s = rowptr[node], e2 = rowptr[node + 1];
    float4 acc = make_float4(0.f, 0.f, 0.f, 0.f);
    for (int j = s; j < e2; j++) {
        int2 ed = __ldg(&csr[j]);
        float w = __int_as_float(ed.y);
        float4 v = *reinterpret_cast<const float4*>(x + ((size_t)ed.x << 7) + lane * 4);
        acc.x += w * v.x; acc.y += w * v.y; acc.z += w * v.z; acc.w += w * v.w;
    }
    __nv_bfloat16 h0 = __float2bfloat16(acc.x), h1 = __float2bfloat16(acc.y);
    __nv_bfloat16 h2 = __float2bfloat16(acc.z), h3 = __float2bfloat16(acc.w);
    size_t o = ((size_t)node << 7) + lane * 4;
    *reinterpret_cast<__nv_bfloat162*>(ah + o)     = __nv_bfloat162(h0, h1);
    *reinterpret_cast<__nv_bfloat162*>(ah + o + 2) = __nv_bfloat162(h2, h3);
    *reinterpret_cast<__nv_bfloat162*>(al + o) = __nv_bfloat162(
        __float2bfloat16(acc.x - __bfloat162float(h0)), __float2bfloat16(acc.y - __bfloat162float(h1)));
    *reinterpret_cast<__nv_bfloat162*>(al + o + 2) = __nv_bfloat162(
        __float2bfloat16(acc.z - __bfloat162float(h2)), __float2bfloat16(acc.w - __bfloat162float(h3)));
}

// ---------------- splits / elementwise ----------------
__global__ void split_bf16(const float* __restrict__ in, __nv_bfloat16* __restrict__ hi,
                           __nv_bfloat16* __restrict__ lo, int n)
{
    int i = (blockIdx.x * blockDim.x + threadIdx.x) * 4;
    if (i >= n) return;
    float4 v = *reinterpret_cast<const float4*>(in + i);
    __nv_bfloat16 h0 = __float2bfloat16(v.x), h1 = __float2bfloat16(v.y);
    __nv_bfloat16 h2 = __float2bfloat16(v.z), h3 = __float2bfloat16(v.w);
    *reinterpret_cast<__nv_bfloat162*>(hi + i)     = __nv_bfloat162(h0, h1);
    *reinterpret_cast<__nv_bfloat162*>(hi + i + 2) = __nv_bfloat162(h2, h3);
    *reinterpret_cast<__nv_bfloat162*>(lo + i) = __nv_bfloat162(
        __float2bfloat16(v.x - __bfloat162float(h0)), __float2bfloat16(v.y - __bfloat162float(h1)));
    *reinterpret_cast<__nv_bfloat162*>(lo + i + 2) = __nv_bfloat162(
        __float2bfloat16(v.z - __bfloat162float(h2)), __float2bfloat16(v.w - __bfloat162float(h3)));
}
__global__ void trans_split_128(const float* __restrict__ in, __nv_bfloat16* __restrict__ hi,
                                __nv_bfloat16* __restrict__ lo)
{
    int idx = blockIdx.x * blockDim.x + threadIdx.x;
    if (idx >= 128 * 128) return;
    int n = idx >> 7, k = idx & 127;
    float v = in[k * 128 + n];
    __nv_bfloat16 h = __float2bfloat16(v);
    hi[idx] = h;
    lo[idx] = __float2bfloat16(v - __bfloat162float(h));
}
__global__ void post_emb(float* __restrict__ x, const float* __restrict__ eb,
                         float* __restrict__ hin, __nv_bfloat16* __restrict__ xh,
                         __nv_bfloat16* __restrict__ xl, int total)
{
    int idx = blockIdx.x * blockDim.x + threadIdx.x;
    if (idx >= total) return;
    float v = x[idx] + eb[idx & 127];
    x[idx] = v; hin[idx] = v;
    __nv_bfloat16 h = __float2bfloat16(v);
    xh[idx] = h;
    xl[idx] = __float2bfloat16(v - __bfloat162float(h));
}
__global__ void gru_update(const float* __restrict__ G, const float* __restrict__ Gin,
                           const float* __restrict__ Ghn, const float* __restrict__ bih,
                           const float* __restrict__ bhh, float* __restrict__ x,
                           __nv_bfloat16* __restrict__ xh, __nv_bfloat16* __restrict__ xl, int total)
{
    int idx = blockIdx.x * blockDim.x + threadIdx.x;
    if (idx >= total) return;
    int c = idx & 127;
    size_t row = (size_t)(idx >> 7);
    float rsum = G[row * 256 + c]       + bih[c]       + bhh[c];
    float zsum = G[row * 256 + 128 + c] + bih[128 + c] + bhh[128 + c];
    float in_  = Gin[idx] + bih[256 + c];
    float hn   = Ghn[idx] + bhh[256 + c];
    float r = 1.f / (1.f + expf(-rsum));
    float z = 1.f / (1.f + expf(-zsum));
    float nn = tanhf(in_ + r * hn);
    float xn = (1.f - z) * nn + z * x[idx];
    x[idx] = xn;
    __nv_bfloat16 h = __float2bfloat16(xn);
    xh[idx] = h;
    xl[idx] = __float2bfloat16(xn - __bfloat162float(h));
}

// ---------------- fp32 SGEMM 64x64 (weight prep + mlp) ----------------
__global__ __launch_bounds__(256) void sgemm64(
    const float* __restrict__ A, const float* __restrict__ B,
    const float* __restrict__ bias, float* __restrict__ C,
    int M, int Ncols, int K, int bTrans,
    const float* __restrict__ A2, const float* __restrict__ ascale,
    const float* __restrict__ ashift)
{
    __shared__ float As[16][64];
    __shared__ float Bs[16][64];
    const int tid = threadIdx.x;
    const int bm = blockIdx.y * 64, bn = blockIdx.x * 64;
    const int trow = (tid >> 4) << 2, tcol = (tid & 15) << 2;
    const int aRow = tid >> 2, aCol = (tid & 3) << 2;
    const int bRow = tid >> 4, bCol = (tid & 15) << 2;
    float acc[4][4] = {};

    for (int k0 = 0; k0 < K; k0 += 16) {
        float4 av = make_float4(0.f, 0.f, 0.f, 0.f);
        int gr = bm + aRow;
        if (gr < M) {
            av = *reinterpret_cast<const float4*>(A + (size_t)gr * K + k0 + aCol);
            if (A2 != nullptr) {
                float4 a2 = *reinterpret_cast<const float4*>(A2 + (size_t)gr * K + k0 + aCol);
                int kk = k0 + aCol;
                av.x = av.x * ascale[kk+0] + ashift[kk+0] + a2.x;
                av.y = av.y * ascale[kk+1] + ashift[kk+1] + a2.y;
                av.z = av.z * ascale[kk+2] + ashift[kk+2] + a2.z;
                av.w = av.w * ascale[kk+3] + ashift[kk+3] + a2.w;
            }
        }
        As[aCol+0][aRow] = av.x; As[aCol+1][aRow] = av.y;
        As[aCol+2][aRow] = av.z; As[aCol+3][aRow] = av.w;

        if (!bTrans) {
            int gn = bn + bCol;
            const float* bp = B + (size_t)(k0 + bRow) * Ncols + gn;
            float4 bv = make_float4(0.f, 0.f, 0.f, 0.f);
            if (gn + 3 < Ncols) bv = *reinterpret_cast<const float4*>(bp);
            else {
                if (gn+0 < Ncols) bv.x = bp[0];
                if (gn+1 < Ncols) bv.y = bp[1];
                if (gn+2 < Ncols) bv.z = bp[2];
                if (gn+3 < Ncols) bv.w = bp[3];
            }
            Bs[bRow][bCol+0] = bv.x; Bs[bRow][bCol+1] = bv.y;
            Bs[bRow][bCol+2] = bv.z; Bs[bRow][bCol+3] = bv.w;
        } else {
            int nIdx = tid >> 2, kIdx = (tid & 3) << 2;
            int gn = bn + nIdx;
            float4 bv = make_float4(0.f, 0.f, 0.f, 0.f);
            if (gn < Ncols) bv = *reinterpret_cast<const float4*>(B + (size_t)gn * K + k0 + kIdx);
            Bs[kIdx+0][nIdx] = bv.x; Bs[kIdx+1][nIdx] = bv.y;
            Bs[kIdx+2][nIdx] = bv.z; Bs[kIdx+3][nIdx] = bv.w;
        }
        __syncthreads();
        #pragma unroll
        for (int k = 0; k < 16; k++) {
            float4 a = *reinterpret_cast<const float4*>(&As[k][trow]);
            float4 b = *reinterpret_cast<const float4*>(&Bs[k][tcol]);
            acc[0][0] += a.x*b.x; acc[0][1] += a.x*b.y; acc[0][2] += a.x*b.z; acc[0][3] += a.x*b.w;
            acc[1][0] += a.y*b.x; acc[1][1] += a.y*b.y; acc[1][2] += a.y*b.z; acc[1][3] += a.y*b.w;
            acc[2][0] += a.z*b.x; acc[2][1] += a.z*b.y; acc[2][2] += a.z*b.z; acc[2][3] += a.z*b.w;
            acc[3][0] += a.w*b.x; acc[3][1] += a.w*b.y; acc[3][2] += a.w*b.z; acc[3][3] += a.w*b.w;
        }
        __syncthreads();
    }
    #pragma unroll
    for (int i = 0; i < 4; i++) {
        int gr = bm + trow + i;
        if (gr >= M) continue;
        #pragma unroll
        for (int j = 0; j < 4; j++) {
            int gn = bn + tcol + j;
            if (gn < Ncols) {
                float v = acc[i][j];
                if (bias != nullptr) v += bias[gn];
                C[(size_t)gr * Ncols + gn] = v;
            }
        }
    }
}

// ---------------- misc ----------------
__global__ void detect_idx_dtype(const long long* __restrict__ ei64, int M, int* __restrict__ flag)
{
    __shared__ int bad;
    if (threadIdx.x == 0) bad = 0;
    __syncthreads();
    long long v = ei64[threadIdx.x];
    if (v < 0 || v >= (long long)M) bad = 1;
    __syncthreads();
    if (threadIdx.x == 0) *flag = bad;
}
__global__ void convert_idx(const void* __restrict__ ei, int twoE,
                            const int* __restrict__ flag, int* __restrict__ out)
{
    int i = blockIdx.x * blockDim.x + threadIdx.x;
    if (i >= twoE) return;
    out[i] = *flag ? ((const int*)ei)[i] : (int)(((const long long*)ei)[i]);
}
__global__ void zero_kernel(float* __restrict__ p, int n)
{
    int i = blockIdx.x * blockDim.x + threadIdx.x;
    if (i < n) p[i] = 0.f;
}
__global__ void bn_stats(const float* __restrict__ x, float* __restrict__ bnSum,
                         float* __restrict__ bnSq, int M)
{
    int c = threadIdx.x, r0 = blockIdx.x * 128;
    float s = 0.f, sq = 0.f;
    #pragma unroll 4
    for (int i = 0; i < 128; i++) {
        int r = r0 + i;
        if (r < M) { float v = x[(size_t)r * HH + c]; s += v; sq += v * v; }
    }
    atomicAdd(&bnSum[c], s);
    atomicAdd(&bnSq[c], sq);
}
__global__ void bn_final(const float* __restrict__ bnSum, const float* __restrict__ bnSq,
                         const float* __restrict__ gamma, const float* __restrict__ beta,
                         float* __restrict__ scale, float* __restrict__ shift, int M)
{
    int c = threadIdx.x;
    float invN = 1.f / (float)M;
    float mean = bnSum[c] * invN;
    float var = bnSq[c] * invN - mean * mean;
    float sc = gamma[c] * rsqrtf(var + 1e-5f);
    scale[c] = sc;
    shift[c] = beta[c] - mean * sc;
}

// ---------------- launch ----------------
extern "C" void kernel_launch(void* const* d_in, const int* in_sizes, int n_in,
                              void* d_out, int out_size)
{
    const float* h      = (const float*)d_in[0];
    const void*  ei_raw = d_in[1];
    const float* ew     = (const float*)d_in[2];
    const float* emb_W  = (const float*)d_in[3];
    const float* emb_b  = (const float*)d_in[4];
    const float* conv_w = (const float*)d_in[5];
    const float* Wih    = (const float*)d_in[6];
    const float* Whh    = (const float*)d_in[7];
    const float* bih    = (const float*)d_in[8];
    const float* bhh    = (const float*)d_in[9];
    const float* gamma  = (const float*)d_in[10];
    const float* beta   = (const float*)d_in[11];
    const float* mlp_W  = (const float*)d_in[12];
    const float* mlp_b  = (const float*)d_in[13];
    float* out = (float*)d_out;

    const int M = in_sizes[0] / FIN;
    const int E = in_sizes[2];

    float *px, *phin, *pG, *pgn, *pbn, *pscale, *pshift, *pwgf;
    __nv_bfloat16 *pxh, *pxl, *pah, *pal, *pwgh, *pwgl, *pwhh, *pwhl, *peth, *petl;
    int *pei, *pflag, *pdeg, *prow, *pcur;
    int2* pcsr;
    cudaGetSymbolAddress((void**)&px, g_x);       cudaGetSymbolAddress((void**)&phin, g_hin);
    cudaGetSymbolAddress((void**)&pG, g_G);       cudaGetSymbolAddress((void**)&pgn, g_gn);
    cudaGetSymbolAddress((void**)&pbn, g_bnstats);
    cudaGetSymbolAddress((void**)&pscale, g_scale); cudaGetSymbolAddress((void**)&pshift, g_shift);
    cudaGetSymbolAddress((void**)&pxh, g_xh);     cudaGetSymbolAddress((void**)&pxl, g_xl);
    cudaGetSymbolAddress((void**)&pah, g_ah);     cudaGetSymbolAddress((void**)&pal, g_al);
    cudaGetSymbolAddress((void**)&pwgf, g_wgf);
    cudaGetSymbolAddress((void**)&pwgh, g_wgh);   cudaGetSymbolAddress((void**)&pwgl, g_wgl);
    cudaGetSymbolAddress((void**)&pwhh, g_whh);   cudaGetSymbolAddress((void**)&pwhl, g_whl);
    cudaGetSymbolAddress((void**)&peth, g_eth);   cudaGetSymbolAddress((void**)&petl, g_etl);
    cudaGetSymbolAddress((void**)&pei, g_ei);     cudaGetSymbolAddress((void**)&pflag, g_flag);
    cudaGetSymbolAddress((void**)&pdeg, g_deg);   cudaGetSymbolAddress((void**)&prow, g_rowptr);
    cudaGetSymbolAddress((void**)&pcur, g_cursor); cudaGetSymbolAddress((void**)&pcsr, g_csr);

    cudaFuncSetAttribute(mma_gemm, cudaFuncAttributeMaxDynamicSharedMemorySize, SMEM_MMA);
    cudaFuncSetAttribute(mma_gemm_gru, cudaFuncAttributeMaxDynamicSharedMemorySize, SMEM_GRU);

    const int total = M * HH;
    const int mb = (M + 127) / 128;

    // 0. edge index conversion + CSR build (by dst)
    detect_idx_dtype<<<1, 1024>>>((const long long*)ei_raw, M, pflag);
    convert_idx<<<(2 * E + 255) / 256, 256>>>(ei_raw, 2 * E, pflag, pei);
    zero_int<<<(M + 255) / 256, 256>>>(pdeg, M);
    count_deg<<<(E + 255) / 256, 256>>>(pei, pdeg, E);
    scan_deg<<<1, 1024>>>(pdeg, prow, pcur, M);
    fill_csr<<<(E + 255) / 256, 256>>>(pei, ew, pcur, pcsr, E);

    // weight prep: Wg[l] = Wih @ conv_w[l]^T ([384,128]); splits
    split_bf16<<<(384 * 128 / 4 + 255) / 256, 256>>>(Whh, pwhh, pwhl, 384 * 128);
    trans_split_128<<<(128 * 128 + 255) / 256, 256>>>(emb_W, peth, petl);
    for (int l = 0; l < LL; l++) {
        sgemm64<<<dim3(2, 6), 256>>>(Wih, conv_w + (size_t)l * 128 * 128, nullptr,
                                     pwgf + (size_t)l * 384 * 128, 384, 128, 128, 1,
                                     nullptr, nullptr, nullptr);
        split_bf16<<<(384 * 128 / 4 + 255) / 256, 256>>>(
            pwgf + (size_t)l * 384 * 128, pwgh + (size_t)l * 384 * 128,
            pwgl + (size_t)l * 384 * 128, 384 * 128);
    }

    // 1. x = h @ emb_W + b, residual + split
    split_bf16<<<(total / 4 + 255) / 256, 256>>>(h, pah, pal, total);
    mma_gemm<<<mb, 256, SMEM_MMA>>>(pah, pal, peth, petl, px, M);
    post_emb<<<(total + 255) / 256, 256>>>(px, emb_b, phin, pxh, pxl, total);

    // 2. GRU layers: CSR aggregate (writes bf16 split) -> fused gi+gh GEMM -> update
    for (int l = 0; l < LL; l++) {
        csr_aggregate<<<(M * 32 + 255) / 256, 256>>>(prow, pcsr, px, pah, pal, M);
        mma_gemm_gru<<<mb, 256, SMEM_GRU>>>(
            pah, pal, pxh, pxl,
            pwgh + (size_t)l * 384 * 128, pwgl + (size_t)l * 384 * 128,
            pwhh, pwhl, pG, pgn, pgn + total, M);
        gru_update<<<(total + 255) / 256, 256>>>(pG, pgn, pgn + total, bih, bhh,
                                                 px, pxh, pxl, total);
    }

    // 3. BN -> scale/shift
    zero_kernel<<<1, 256>>>(pbn, 2 * HH);
    bn_stats<<<(M + 127) / 128, 128>>>(px, pbn, pbn + HH, M);
    bn_final<<<1, HH>>>(pbn, pbn + HH, gamma, beta, pscale, pshift, M);

    // 4. out = (BN(x) + h_in) @ mlp_W + mlp_b  (fp32, BN+residual fused)
    sgemm64<<<dim3(1, (M + 63) / 64), 256>>>(
        px, mlp_W, mlp_b, out, M, CC, FIN, 0, phin, pscale, pshift);
}

// round 17
// speedup vs baseline: 2.0289x; 1.1592x over previous
#include <cuda_runtime.h>
#include <cuda_bf16.h>
#include <cstdint>

#define NNODE_MAX 100000
#define EDGE_MAX  3200000
#define HH 128
#define FIN 128
#define CC 40
#define LL 3

// ---------------- scratch ----------------
__device__ float g_x[(size_t)NNODE_MAX * HH];
__device__ float g_hin[(size_t)NNODE_MAX * HH];
__device__ float g_gi[(size_t)NNODE_MAX * 3 * HH];
__device__ float g_gh[(size_t)NNODE_MAX * 3 * HH];
__device__ __nv_bfloat16 g_xh[(size_t)NNODE_MAX * HH];
__device__ __nv_bfloat16 g_xl[(size_t)NNODE_MAX * HH];
__device__ __nv_bfloat16 g_ah[(size_t)NNODE_MAX * HH];
__device__ __nv_bfloat16 g_al[(size_t)NNODE_MAX * HH];
__device__ float         g_wgf[3 * 384 * 128];
__device__ __nv_bfloat16 g_wgh[3 * 384 * 128], g_wgl[3 * 384 * 128];
__device__ __nv_bfloat16 g_whh[384 * 128], g_whl[384 * 128];
__device__ __nv_bfloat16 g_eth[128 * 128], g_etl[128 * 128];
__device__ float g_bnstats[2 * HH];
__device__ float g_scale[HH], g_shift[HH];
__device__ int   g_ei[(size_t)2 * EDGE_MAX];
__device__ int   g_flag[1];
__device__ int   g_deg[NNODE_MAX];
__device__ int   g_rowptr[NNODE_MAX + 1];
__device__ int   g_cursor[NNODE_MAX];
__device__ int2  g_csr[EDGE_MAX];

// ---------------- mma helpers ----------------
__device__ __forceinline__ uint32_t smem_u32(const void* p) {
    uint32_t a;
    asm("{ .reg .u64 t; cvta.to.shared.u64 t, %1; cvt.u32.u64 %0, t; }" : "=r"(a) : "l"(p));
    return a;
}
__device__ __forceinline__ void ldsm4(uint32_t addr, uint32_t* r) {
    asm volatile("ldmatrix.sync.aligned.m8n8.x4.shared.b16 {%0,%1,%2,%3}, [%4];"
        : "=r"(r[0]), "=r"(r[1]), "=r"(r[2]), "=r"(r[3]) : "r"(addr));
}
__device__ __forceinline__ void mma16816(float* d, const uint32_t* a, uint32_t b0, uint32_t b1) {
    asm volatile("mma.sync.aligned.m16n8k16.row.col.f32.bf16.bf16.f32 "
        "{%0,%1,%2,%3}, {%4,%5,%6,%7}, {%8,%9}, {%0,%1,%2,%3};"
        : "+f"(d[0]), "+f"(d[1]), "+f"(d[2]), "+f"(d[3])
        : "r"(a[0]), "r"(a[1]), "r"(a[2]), "r"(a[3]), "r"(b0), "r"(b1));
}
#define TILE_BYTES 32768

__device__ __forceinline__ void load_tile(const __nv_bfloat16* __restrict__ g,
                                          int row0, int maxRow, char* dst) {
    for (int idx = threadIdx.x; idx < 2048; idx += 256) {
        int r = idx >> 4, cc = idx & 15;
        uint4 v = make_uint4(0u, 0u, 0u, 0u);
        int gr = row0 + r;
        if (gr < maxRow) v = *reinterpret_cast<const uint4*>(g + (size_t)gr * 128 + cc * 8);
        *reinterpret_cast<uint4*>(dst + r * 256 + ((cc ^ (r & 7)) * 16)) = v;
    }
}
__device__ __forceinline__ void mma_block(uint32_t aBase, uint32_t bBase, int wm0, int wn0,
                                          int lri, int lch, float (&acc)[2][8][4]) {
    #pragma unroll
    for (int ks = 0; ks < 8; ks++) {
        const int chunk = ks * 2 + lch;
        uint32_t a[2][4], b[4][4];
        #pragma unroll
        for (int i = 0; i < 2; i++) {
            int row = wm0 + i * 16 + lri;
            ldsm4(aBase + row * 256 + ((chunk ^ (row & 7)) * 16), a[i]);
        }
        #pragma unroll
        for (int j = 0; j < 4; j++) {
            int row = wn0 + j * 16 + lri;
            ldsm4(bBase + row * 256 + ((chunk ^ (row & 7)) * 16), b[j]);
        }
        #pragma unroll
        for (int i = 0; i < 2; i++)
            #pragma unroll
            for (int j = 0; j < 4; j++) {
                mma16816(acc[i][2 * j],     a[i], b[j][0], b[j][2]);
                mma16816(acc[i][2 * j + 1], a[i], b[j][1], b[j][3]);
            }
    }
}

// ---- generic 3-term split GEMM: C[M,N] = (Ah+Al)[M,128].(Bh+Bl)[N,128]^T ----
#define SMEM_MMA (4 * TILE_BYTES)
__global__ __launch_bounds__(256, 1)
void mma_gemm_n(const __nv_bfloat16* __restrict__ Ah, const __nv_bfloat16* __restrict__ Al,
                const __nv_bfloat16* __restrict__ Bh, const __nv_bfloat16* __restrict__ Bl,
                float* __restrict__ C, int M, int N)
{
    extern __shared__ char smem[];
    const uint32_t sbA = smem_u32(smem), sbB = smem_u32(smem + 2 * TILE_BYTES);
    const int tid = threadIdx.x, wid = tid >> 5, lane = tid & 31;
    const int wm0 = (wid >> 1) * 32, wn0 = (wid & 1) * 64;
    const int lg = lane >> 3, lri = (lane & 7) + ((lg & 1) << 3), lch = lg >> 1;
    const int bm = blockIdx.x * 128;

    load_tile(Ah, bm, M, smem);
    load_tile(Al, bm, M, smem + TILE_BYTES);

    const int nch = N >> 7;
    for (int nc = 0; nc < nch; nc++) {
        __syncthreads();   // A stores visible (nc=0); prior B consumers done (nc>0)
        load_tile(Bh, nc * 128, N, smem + 2 * TILE_BYTES);
        load_tile(Bl, nc * 128, N, smem + 3 * TILE_BYTES);
        __syncthreads();
        float acc[2][8][4];
        #pragma unroll
        for (int i = 0; i < 2; i++)
            #pragma unroll
            for (int j = 0; j < 8; j++)
                #pragma unroll
                for (int q = 0; q < 4; q++) acc[i][j][q] = 0.f;
        mma_block(sbA, sbB, wm0, wn0, lri, lch, acc);
        mma_block(sbA, sbB + TILE_BYTES, wm0, wn0, lri, lch, acc);
        mma_block(sbA + TILE_BYTES, sbB, wm0, wn0, lri, lch, acc);
        const int fr = lane >> 2, fc = (lane & 3) * 2;
        #pragma unroll
        for (int i = 0; i < 2; i++)
            #pragma unroll
            for (int j = 0; j < 8; j++) {
                int col = nc * 128 + wn0 + j * 8 + fc;
                int r0 = bm + wm0 + i * 16 + fr;
                if (r0 < M)
                    *reinterpret_cast<float2*>(C + (size_t)r0 * N + col) =
                        make_float2(acc[i][j][0], acc[i][j][1]);
                if (r0 + 8 < M)
                    *reinterpret_cast<float2*>(C + (size_t)(r0 + 8) * N + col) =
                        make_float2(acc[i][j][2], acc[i][j][3]);
            }
    }
}

// ---------------- CSR build ----------------
__global__ void zero_int(int* __restrict__ p, int n)
{
    int i = blockIdx.x * blockDim.x + threadIdx.x;
    if (i < n) p[i] = 0;
}
__global__ void count_deg(const int* __restrict__ srcdst, int* __restrict__ deg, int E)
{
    int e = blockIdx.x * blockDim.x + threadIdx.x;
    if (e < E) atomicAdd(&deg[srcdst[E + e]], 1);
}
__global__ void scan_deg(const int* __restrict__ deg, int* __restrict__ rowptr,
                         int* __restrict__ cursor, int M)
{
    __shared__ int s[1024];
    __shared__ int carry;
    if (threadIdx.x == 0) { carry = 0; rowptr[0] = 0; }
    __syncthreads();
    for (int base = 0; base < M; base += 1024) {
        int i = base + threadIdx.x;
        int v = (i < M) ? deg[i] : 0;
        s[threadIdx.x] = v;
        __syncthreads();
        #pragma unroll
        for (int off = 1; off < 1024; off <<= 1) {
            int t = (threadIdx.x >= off) ? s[threadIdx.x - off] : 0;
            __syncthreads();
            s[threadIdx.x] += t;
            __syncthreads();
        }
        if (i < M) {
            int incl = carry + s[threadIdx.x];
            rowptr[i + 1] = incl;
            cursor[i] = incl - v;
        }
        __syncthreads();
        if (threadIdx.x == 0) carry += s[1023];
        __syncthreads();
    }
}
__global__ void fill_csr(const int* __restrict__ srcdst, const float* __restrict__ ew,
                         int* __restrict__ cursor, int2* __restrict__ csr, int E)
{
    int e = blockIdx.x * blockDim.x + threadIdx.x;
    if (e >= E) return;
    int pos = atomicAdd(&cursor[srcdst[E + e]], 1);
    csr[pos] = make_int2(srcdst[e], __float_as_int(ew[e]));
}

// ---- aggregate: warp/node, 2-edge pipeline; writes bf16 hi/lo split ----
__global__ void csr_aggregate(const int* __restrict__ rowptr, const int2* __restrict__ csr,
                              const float* __restrict__ x, __nv_bfloat16* __restrict__ ah,
                              __nv_bfloat16* __restrict__ al, int M)
{
    int node = (int)((blockIdx.x * blockDim.x + threadIdx.x) >> 5);
    if (node >= M) return;
    int lane = threadIdx.x & 31;
    int s = rowptr[node], e2 = rowptr[node + 1];
    float4 acc = make_float4(0.f, 0.f, 0.f, 0.f);
    int j = s;
    for (; j + 2 <= e2; j += 2) {
        int2 e0 = __ldg(&csr[j]);
        int2 e1 = __ldg(&csr[j + 1]);
        float4 v0 = *reinterpret_cast<const float4*>(x + ((size_t)e0.x << 7) + lane * 4);
        float4 v1 = *reinterpret_cast<const float4*>(x + ((size_t)e1.x << 7) + lane * 4);
        float w0 = __int_as_float(e0.y), w1 = __int_as_float(e1.y);
        acc.x += w0 * v0.x + w1 * v1.x;
        acc.y += w0 * v0.y + w1 * v1.y;
        acc.z += w0 * v0.z + w1 * v1.z;
        acc.w += w0 * v0.w + w1 * v1.w;
    }
    if (j < e2) {
        int2 e0 = __ldg(&csr[j]);
        float w0 = __int_as_float(e0.y);
        float4 v0 = *reinterpret_cast<const float4*>(x + ((size_t)e0.x << 7) + lane * 4);
        acc.x += w0 * v0.x; acc.y += w0 * v0.y; acc.z += w0 * v0.z; acc.w += w0 * v0.w;
    }
    __nv_bfloat16 h0 = __float2bfloat16(acc.x), h1 = __float2bfloat16(acc.y);
    __nv_bfloat16 h2 = __float2bfloat16(acc.z), h3 = __float2bfloat16(acc.w);
    size_t o = ((size_t)node << 7) + lane * 4;
    *reinterpret_cast<__nv_bfloat162*>(ah + o)     = __nv_bfloat162(h0, h1);
    *reinterpret_cast<__nv_bfloat162*>(ah + o + 2) = __nv_bfloat162(h2, h3);
    *reinterpret_cast<__nv_bfloat162*>(al + o) = __nv_bfloat162(
        __float2bfloat16(acc.x - __bfloat162float(h0)), __float2bfloat16(acc.y - __bfloat162float(h1)));
    *reinterpret_cast<__nv_bfloat162*>(al + o + 2) = __nv_bfloat162(
        __float2bfloat16(acc.z - __bfloat162float(h2)), __float2bfloat16(acc.w - __bfloat162float(h3)));
}

// ---------------- splits / elementwise ----------------
__global__ void split_bf16(const float* __restrict__ in, __nv_bfloat16* __restrict__ hi,
                           __nv_bfloat16* __restrict__ lo, int n)
{
    int i = (blockIdx.x * blockDim.x + threadIdx.x) * 4;
    if (i >= n) return;
    float4 v = *reinterpret_cast<const float4*>(in + i);
    __nv_bfloat16 h0 = __float2bfloat16(v.x), h1 = __float2bfloat16(v.y);
    __nv_bfloat16 h2 = __float2bfloat16(v.z), h3 = __float2bfloat16(v.w);
    *reinterpret_cast<__nv_bfloat162*>(hi + i)     = __nv_bfloat162(h0, h1);
    *reinterpret_cast<__nv_bfloat162*>(hi + i + 2) = __nv_bfloat162(h2, h3);
    *reinterpret_cast<__nv_bfloat162*>(lo + i) = __nv_bfloat162(
        __float2bfloat16(v.x - __bfloat162float(h0)), __float2bfloat16(v.y - __bfloat162float(h1)));
    *reinterpret_cast<__nv_bfloat162*>(lo + i + 2) = __nv_bfloat162(
        __float2bfloat16(v.z - __bfloat162float(h2)), __float2bfloat16(v.w - __bfloat162float(h3)));
}
__global__ void trans_split_128(const float* __restrict__ in, __nv_bfloat16* __restrict__ hi,
                                __nv_bfloat16* __restrict__ lo)
{
    int idx = blockIdx.x * blockDim.x + threadIdx.x;
    if (idx >= 128 * 128) return;
    int n = idx >> 7, k = idx & 127;
    float v = in[k * 128 + n];
    __nv_bfloat16 h = __float2bfloat16(v);
    hi[idx] = h;
    lo[idx] = __float2bfloat16(v - __bfloat162float(h));
}
__global__ void post_emb(float* __restrict__ x, const float* __restrict__ eb,
                         float* __restrict__ hin, __nv_bfloat16* __restrict__ xh,
                         __nv_bfloat16* __restrict__ xl, int total)
{
    int idx = blockIdx.x * blockDim.x + threadIdx.x;
    if (idx >= total) return;
    float v = x[idx] + eb[idx & 127];
    x[idx] = v; hin[idx] = v;
    __nv_bfloat16 h = __float2bfloat16(v);
    xh[idx] = h;
    xl[idx] = __float2bfloat16(v - __bfloat162float(h));
}
__global__ void gru_update(const float* __restrict__ gi, const float* __restrict__ gh,
                           const float* __restrict__ bih, const float* __restrict__ bhh,
                           float* __restrict__ x, __nv_bfloat16* __restrict__ xh,
                           __nv_bfloat16* __restrict__ xl, int total)
{
    int idx = blockIdx.x * blockDim.x + threadIdx.x;
    if (idx >= total) return;
    int c = idx & 127;
    size_t b = (size_t)(idx >> 7) * 384;
    float rsum = gi[b + c]       + gh[b + c]       + bih[c]       + bhh[c];
    float zsum = gi[b + 128 + c] + gh[b + 128 + c] + bih[128 + c] + bhh[128 + c];
    float in_  = gi[b + 256 + c] + bih[256 + c];
    float hn   = gh[b + 256 + c] + bhh[256 + c];
    float r = 1.f / (1.f + expf(-rsum));
    float z = 1.f / (1.f + expf(-zsum));
    float nn = tanhf(in_ + r * hn);
    float xn = (1.f - z) * nn + z * x[idx];
    x[idx] = xn;
    __nv_bfloat16 h = __float2bfloat16(xn);
    xh[idx] = h;
    xl[idx] = __float2bfloat16(xn - __bfloat162float(h));
}

// ---------------- fp32 SGEMM 64x64 (weight prep + mlp) ----------------
__global__ __launch_bounds__(256) void sgemm64(
    const float* __restrict__ A, const float* __restrict__ B,
    const float* __restrict__ bias, float* __restrict__ C,
    int M, int Ncols, int K, int bTrans,
    const float* __restrict__ A2, const float* __restrict__ ascale,
    const float* __restrict__ ashift)
{
    __shared__ float As[16][64];
    __shared__ float Bs[16][64];
    const int tid = threadIdx.x;
    const int bm = blockIdx.y * 64, bn = blockIdx.x * 64;
    const int trow = (tid >> 4) << 2, tcol = (tid & 15) << 2;
    const int aRow = tid >> 2, aCol = (tid & 3) << 2;
    const int bRow = tid >> 4, bCol = (tid & 15) << 2;
    float acc[4][4] = {};

    for (int k0 = 0; k0 < K; k0 += 16) {
        float4 av = make_float4(0.f, 0.f, 0.f, 0.f);
        int gr = bm + aRow;
        if (gr < M) {
            av = *reinterpret_cast<const float4*>(A + (size_t)gr * K + k0 + aCol);
            if (A2 != nullptr) {
                float4 a2 = *reinterpret_cast<const float4*>(A2 + (size_t)gr * K + k0 + aCol);
                int kk = k0 + aCol;
                av.x = av.x * ascale[kk+0] + ashift[kk+0] + a2.x;
                av.y = av.y * ascale[kk+1] + ashift[kk+1] + a2.y;
                av.z = av.z * ascale[kk+2] + ashift[kk+2] + a2.z;
                av.w = av.w * ascale[kk+3] + ashift[kk+3] + a2.w;
            }
        }
        As[aCol+0][aRow] = av.x; As[aCol+1][aRow] = av.y;
        As[aCol+2][aRow] = av.z; As[aCol+3][aRow] = av.w;

        if (!bTrans) {
            int gn = bn + bCol;
            const float* bp = B + (size_t)(k0 + bRow) * Ncols + gn;
            float4 bv = make_float4(0.f, 0.f, 0.f, 0.f);
            if (gn + 3 < Ncols) bv = *reinterpret_cast<const float4*>(bp);
            else {
                if (gn+0 < Ncols) bv.x = bp[0];
                if (gn+1 < Ncols) bv.y = bp[1];
                if (gn+2 < Ncols) bv.z = bp[2];
                if (gn+3 < Ncols) bv.w = bp[3];
            }
            Bs[bRow][bCol+0] = bv.x; Bs[bRow][bCol+1] = bv.y;
            Bs[bRow][bCol+2] = bv.z; Bs[bRow][bCol+3] = bv.w;
        } else {
            int nIdx = tid >> 2, kIdx = (tid & 3) << 2;
            int gn = bn + nIdx;
            float4 bv = make_float4(0.f, 0.f, 0.f, 0.f);
            if (gn < Ncols) bv = *reinterpret_cast<const float4*>(B + (size_t)gn * K + k0 + kIdx);
            Bs[kIdx+0][nIdx] = bv.x; Bs[kIdx+1][nIdx] = bv.y;
            Bs[kIdx+2][nIdx] = bv.z; Bs[kIdx+3][nIdx] = bv.w;
        }
        __syncthreads();
        #pragma unroll
        for (int k = 0; k < 16; k++) {
            float4 a = *reinterpret_cast<const float4*>(&As[k][trow]);
            float4 b = *reinterpret_cast<const float4*>(&Bs[k][tcol]);
            acc[0][0] += a.x*b.x; acc[0][1] += a.x*b.y; acc[0][2] += a.x*b.z; acc[0][3] += a.x*b.w;
            acc[1][0] += a.y*b.x; acc[1][1] += a.y*b.y; acc[1][2] += a.y*b.z; acc[1][3] += a.y*b.w;
            acc[2][0] += a.z*b.x; acc[2][1] += a.z*b.y; acc[2][2] += a.z*b.z; acc[2][3] += a.z*b.w;
            acc[3][0] += a.w*b.x; acc[3][1] += a.w*b.y; acc[3][2] += a.w*b.z; acc[3][3] += a.w*b.w;
        }
        __syncthreads();
    }
    #pragma unroll
    for (int i = 0; i < 4; i++) {
        int gr = bm + trow + i;
        if (gr >= M) continue;
        #pragma unroll
        for (int j = 0; j < 4; j++) {
            int gn = bn + tcol + j;
            if (gn < Ncols) {
                float v = acc[i][j];
                if (bias != nullptr) v += bias[gn];
                C[(size_t)gr * Ncols + gn] = v;
            }
        }
    }
}

// ---------------- misc ----------------
__global__ void detect_idx_dtype(const long long* __restrict__ ei64, int M, int* __restrict__ flag)
{
    __shared__ int bad;
    if (threadIdx.x == 0) bad = 0;
    __syncthreads();
    long long v = ei64[threadIdx.x];
    if (v < 0 || v >= (long long)M) bad = 1;
    __syncthreads();
    if (threadIdx.x == 0) *flag = bad;
}
__global__ void convert_idx(const void* __restrict__ ei, int twoE,
                            const int* __restrict__ flag, int* __restrict__ out)
{
    int i = blockIdx.x * blockDim.x + threadIdx.x;
    if (i >= twoE) return;
    out[i] = *flag ? ((const int*)ei)[i] : (int)(((const long long*)ei)[i]);
}
__global__ void zero_kernel(float* __restrict__ p, int n)
{
    int i = blockIdx.x * blockDim.x + threadIdx.x;
    if (i < n) p[i] = 0.f;
}
__global__ void bn_stats(const float* __restrict__ x, float* __restrict__ bnSum,
                         float* __restrict__ bnSq, int M)
{
    int c = threadIdx.x, r0 = blockIdx.x * 128;
    float s = 0.f, sq = 0.f;
    #pragma unroll 4
    for (int i = 0; i < 128; i++) {
        int r = r0 + i;
        if (r < M) { float v = x[(size_t)r * HH + c]; s += v; sq += v * v; }
    }
    atomicAdd(&bnSum[c], s);
    atomicAdd(&bnSq[c], sq);
}
__global__ void bn_final(const float* __restrict__ bnSum, const float* __restrict__ bnSq,
                         const float* __restrict__ gamma, const float* __restrict__ beta,
                         float* __restrict__ scale, float* __restrict__ shift, int M)
{
    int c = threadIdx.x;
    float invN = 1.f / (float)M;
    float mean = bnSum[c] * invN;
    float var = bnSq[c] * invN - mean * mean;
    float sc = gamma[c] * rsqrtf(var + 1e-5f);
    scale[c] = sc;
    shift[c] = beta[c] - mean * sc;
}

// ---------------- launch ----------------
extern "C" void kernel_launch(void* const* d_in, const int* in_sizes, int n_in,
                              void* d_out, int out_size)
{
    const float* h      = (const float*)d_in[0];
    const void*  ei_raw = d_in[1];
    const float* ew     = (const float*)d_in[2];
    const float* emb_W  = (const float*)d_in[3];
    const float* emb_b  = (const float*)d_in[4];
    const float* conv_w = (const float*)d_in[5];
    const float* Wih    = (const float*)d_in[6];
    const float* Whh    = (const float*)d_in[7];
    const float* bih    = (const float*)d_in[8];
    const float* bhh    = (const float*)d_in[9];
    const float* gamma  = (const float*)d_in[10];
    const float* beta   = (const float*)d_in[11];
    const float* mlp_W  = (const float*)d_in[12];
    const float* mlp_b  = (const float*)d_in[13];
    float* out = (float*)d_out;

    const int M = in_sizes[0] / FIN;
    const int E = in_sizes[2];

    float *px, *phin, *pgi, *pgh, *pbn, *pscale, *pshift, *pwgf;
    __nv_bfloat16 *pxh, *pxl, *pah, *pal, *pwgh, *pwgl, *pwhh, *pwhl, *peth, *petl;
    int *pei, *pflag, *pdeg, *prow, *pcur;
    int2* pcsr;
    cudaGetSymbolAddress((void**)&px, g_x);       cudaGetSymbolAddress((void**)&phin, g_hin);
    cudaGetSymbolAddress((void**)&pgi, g_gi);     cudaGetSymbolAddress((void**)&pgh, g_gh);
    cudaGetSymbolAddress((void**)&pbn, g_bnstats);
    cudaGetSymbolAddress((void**)&pscale, g_scale); cudaGetSymbolAddress((void**)&pshift, g_shift);
    cudaGetSymbolAddress((void**)&pxh, g_xh);     cudaGetSymbolAddress((void**)&pxl, g_xl);
    cudaGetSymbolAddress((void**)&pah, g_ah);     cudaGetSymbolAddress((void**)&pal, g_al);
    cudaGetSymbolAddress((void**)&pwgf, g_wgf);
    cudaGetSymbolAddress((void**)&pwgh, g_wgh);   cudaGetSymbolAddress((void**)&pwgl, g_wgl);
    cudaGetSymbolAddress((void**)&pwhh, g_whh);   cudaGetSymbolAddress((void**)&pwhl, g_whl);
    cudaGetSymbolAddress((void**)&peth, g_eth);   cudaGetSymbolAddress((void**)&petl, g_etl);
    cudaGetSymbolAddress((void**)&pei, g_ei);     cudaGetSymbolAddress((void**)&pflag, g_flag);
    cudaGetSymbolAddress((void**)&pdeg, g_deg);   cudaGetSymbolAddress((void**)&prow, g_rowptr);
    cudaGetSymbolAddress((void**)&pcur, g_cursor); cudaGetSymbolAddress((void**)&pcsr, g_csr);

    cudaFuncSetAttribute(mma_gemm_n, cudaFuncAttributeMaxDynamicSharedMemorySize, SMEM_MMA);

    // static second stream + fork/join events (created on first, uncaptured call)
    static cudaStream_t s2 = nullptr;
    static cudaEvent_t evF = nullptr, evP = nullptr, evG = nullptr;
    if (s2 == nullptr) {
        cudaStreamCreateWithFlags(&s2, cudaStreamNonBlocking);
        cudaEventCreateWithFlags(&evF, cudaEventDisableTiming);
        cudaEventCreateWithFlags(&evP, cudaEventDisableTiming);
        cudaEventCreateWithFlags(&evG, cudaEventDisableTiming);
    }

    const int total = M * HH;
    const int mb = (M + 127) / 128;

    // fork: s2 runs weight prep + embedding chain while stream 0 builds CSR
    cudaEventRecord(evF, 0);
    cudaStreamWaitEvent(s2, evF, 0);

    // -- s2: weight prep (Wg[l] = Wih @ conv_w[l]^T), splits, emb GEMM, post_emb
    split_bf16<<<(384 * 128 / 4 + 255) / 256, 256, 0, s2>>>(Whh, pwhh, pwhl, 384 * 128);
    trans_split_128<<<(128 * 128 + 255) / 256, 256, 0, s2>>>(emb_W, peth, petl);
    for (int l = 0; l < LL; l++) {
        sgemm64<<<dim3(2, 6), 256, 0, s2>>>(Wih, conv_w + (size_t)l * 128 * 128, nullptr,
                                            pwgf + (size_t)l * 384 * 128, 384, 128, 128, 1,
                                            nullptr, nullptr, nullptr);
        split_bf16<<<(384 * 128 / 4 + 255) / 256, 256, 0, s2>>>(
            pwgf + (size_t)l * 384 * 128, pwgh + (size_t)l * 384 * 128,
            pwgl + (size_t)l * 384 * 128, 384 * 128);
    }
    split_bf16<<<(total / 4 + 255) / 256, 256, 0, s2>>>(h, pah, pal, total);
    mma_gemm_n<<<mb, 256, SMEM_MMA, s2>>>(pah, pal, peth, petl, px, M, 128);
    post_emb<<<(total + 255) / 256, 256, 0, s2>>>(px, emb_b, phin, pxh, pxl, total);
    cudaEventRecord(evP, s2);

    // -- stream 0: edge index conversion + CSR build (independent of s2 chain)
    detect_idx_dtype<<<1, 1024>>>((const long long*)ei_raw, M, pflag);
    convert_idx<<<(2 * E + 255) / 256, 256>>>(ei_raw, 2 * E, pflag, pei);
    zero_int<<<(M + 255) / 256, 256>>>(pdeg, M);
    count_deg<<<(E + 255) / 256, 256>>>(pei, pdeg, E);
    scan_deg<<<1, 1024>>>(pdeg, prow, pcur, M);
    fill_csr<<<(E + 255) / 256, 256>>>(pei, ew, pcur, pcsr, E);
    cudaStreamWaitEvent(0, evP, 0);   // join: x/xh/xl + weights ready

    // GRU layers: gh on s2 overlaps aggregate+gi on stream 0
    for (int l = 0; l < LL; l++) {
        if (l > 0) {               // x from gru_update(l-1) on stream 0
            cudaEventRecord(evF, 0);
            cudaStreamWaitEvent(s2, evF, 0);
        }                          // l==0: s2 already ordered after post_emb
        mma_gemm_n<<<mb, 256, SMEM_MMA, s2>>>(pxh, pxl, pwhh, pwhl, pgh, M, 384);
        cudaEventRecord(evG, s2);

        csr_aggregate<<<(M * 32 + 255) / 256, 256>>>(prow, pcsr, px, pah, pal, M);
        mma_gemm_n<<<mb, 256, SMEM_MMA>>>(pah, pal, pwgh + (size_t)l * 384 * 128,
                                          pwgl + (size_t)l * 384 * 128, pgi, M, 384);
        cudaStreamWaitEvent(0, evG, 0);
        gru_update<<<(total + 255) / 256, 256>>>(pgi, pgh, bih, bhh, px, pxh, pxl, total);
    }

    // BN -> scale/shift; mlp with BN+residual fused
    zero_kernel<<<1, 256>>>(pbn, 2 * HH);
    bn_stats<<<(M + 127) / 128, 128>>>(px, pbn, pbn + HH, M);
    bn_final<<<1, HH>>>(pbn, pbn + HH, gamma, beta, pscale, pshift, M);
    sgemm64<<<dim3(1, (M + 63) / 64), 256>>>(
        px, mlp_W, mlp_b, out, M, CC, FIN, 0, phin, pscale, pshift);
}